// round 15
// baseline (speedup 1.0000x reference)
#include <cuda_runtime.h>

// MultiScaleTrendLoss: loss = mean_{b,t,c} sum_i w_i * ema(pred-target, a_i)[b,t,c]^2
// Exact chunked EMA: y_k = z_k + beta^{k+1} * C.
// K1: 8 warps/block = 8 consecutive 64-row chunks of one b; P=8 register
// prefetch pipeline (16 LDGs in flight/warp -> saturate DRAM at ~25 warps/SM).
// Per-chunk (S,E) -> smem -> folded to one 512-row segment (P,Q,L). 1.2 MB to
// global. K2: 8-segment carry scan per chain + deterministic ticket reduce.

#define BB 64
#define TT 4096
#define CC 64
#define CHUNK 64
#define NCHUNK (TT / CHUNK)             // 64
#define WPB 8                           // warps (=chunks) per k1 block
#define NBSEG (NCHUNK / WPB)            // 8 block-segments per b
#define GRID1 (BB * NBSEG)              // 512
#define THREADS 256
#define NCHAIN (3 * 2 * BB * 32)        // 12288 chains (ac, b, lane)
#define GRID2 (NCHAIN / 32)             // 384
#define THREADS2 256

#define AL0 0.1f
#define AL1 0.3f
#define AL2 0.5f
#define BE0 0.9f
#define BE1 0.7f
#define BE2 0.5f
#define W0f 0.5f
#define W1f 0.3f
#define W2f 0.2f

__host__ __device__ constexpr double dpow(double b, int n) {
    double r = 1.0; for (int i = 0; i < n; ++i) r *= b; return r;
}
__host__ __device__ constexpr double gsum(double beta, int L) {   // sum_{k=1..L} beta^{2k}
    double q = beta * beta; return q * (1.0 - dpow(q, L)) / (1.0 - q);
}
__host__ __device__ constexpr double geo0(double x, int n) {      // sum_{k=0..n-1} x^k
    double s = 0.0, p = 1.0; for (int k = 0; k < n; ++k) { s += p; p *= x; } return s;
}

__device__ __forceinline__ float pick3(int a, float x0, float x1, float x2) {
    return (a == 0) ? x0 : ((a == 1) ? x1 : x2);
}
// chunk-level (64 rows)
#define BL_F(a)   pick3(a, (float)dpow(0.9, CHUNK), (float)dpow(0.7, CHUNK), (float)dpow(0.5, CHUNK))
#define G_F(a)    pick3(a, (float)gsum(0.9, CHUNK), (float)gsum(0.7, CHUNK), (float)gsum(0.5, CHUNK))
// segment-level (512 rows = 8 chunks)
#define M512_F(a) pick3(a, (float)dpow(0.9, CHUNK * WPB), \
                           (float)dpow(0.7, CHUNK * WPB), \
                           (float)dpow(0.5, CHUNK * WPB))
#define R512_F(a) pick3(a, (float)(gsum(0.9, CHUNK) * geo0(dpow(0.9, 2 * CHUNK), WPB)), \
                           (float)(gsum(0.7, CHUNK) * geo0(dpow(0.7, 2 * CHUNK), WPB)), \
                           (float)(gsum(0.5, CHUNK) * geo0(dpow(0.5, 2 * CHUNK), WPB)))
#define W_F(a)    pick3(a, W0f, W1f, W2f)

__device__ float g_P[NBSEG * NCHAIN];
__device__ float g_Q[NBSEG * NCHAIN];
__device__ float g_L[NBSEG * NCHAIN];
__device__ float g_Ap[GRID1];
__device__ float g_D0[2 * BB * 32];
__device__ float g_p2[GRID2];
__device__ unsigned int g_count2 = 0;

// ============ Kernel 1: stream (P=8 pipeline) + block-local segment fold ============
__global__ __launch_bounds__(THREADS) void ema_k1(
    const float* __restrict__ pred, const float* __restrict__ targ)
{
    const int tid  = threadIdx.x;
    const int w    = tid >> 5;
    const int lane = tid & 31;
    const int b    = blockIdx.x >> 3;            // / NBSEG
    const int bs   = blockIdx.x & (NBSEG - 1);
    const int chunk = bs * WPB + w;              // 0..63

    __shared__ float sS[6 * THREADS];            // [ac][w*32+lane]
    __shared__ float sE[6 * THREADS];
    __shared__ float sA[WPB];

    // ---- streaming phase: 8-deep register prefetch pipeline ----
    {
        const float2* __restrict__ p2 = reinterpret_cast<const float2*>(pred)
                                        + (b * TT + chunk * CHUNK) * (CC / 2) + lane;
        const float2* __restrict__ q2 = reinterpret_cast<const float2*>(targ)
                                        + (b * TT + chunk * CHUNK) * (CC / 2) + lane;

        constexpr int P = 8;
        float2 bp[P], bq[P];
        #pragma unroll
        for (int i = 0; i < P; ++i) { bp[i] = p2[i * (CC / 2)]; bq[i] = q2[i * (CC / 2)]; }

        float z0x = 0.f, z0y = 0.f, z1x = 0.f, z1y = 0.f, z2x = 0.f, z2y = 0.f;
        float A0x = 0.f, A0y = 0.f, A1x = 0.f, A1y = 0.f, A2x = 0.f, A2y = 0.f;
        float S0x = 0.f, S0y = 0.f, S1x = 0.f, S1y = 0.f, S2x = 0.f, S2y = 0.f;
        float pw0 = BE0, pw1 = BE1, pw2 = BE2;

        const float d0x = bp[0].x - bq[0].x;
        const float d0y = bp[0].y - bq[0].y;

        auto step = [&](float dx, float dy) {
            z0x = fmaf(AL0, dx - z0x, z0x);  z0y = fmaf(AL0, dy - z0y, z0y);
            z1x = fmaf(AL1, dx - z1x, z1x);  z1y = fmaf(AL1, dy - z1y, z1y);
            z2x = fmaf(AL2, dx - z2x, z2x);  z2y = fmaf(AL2, dy - z2y, z2y);
            A0x = fmaf(z0x, z0x, A0x);  A0y = fmaf(z0y, z0y, A0y);
            A1x = fmaf(z1x, z1x, A1x);  A1y = fmaf(z1y, z1y, A1y);
            A2x = fmaf(z2x, z2x, A2x);  A2y = fmaf(z2y, z2y, A2y);
            S0x = fmaf(pw0, z0x, S0x);  S0y = fmaf(pw0, z0y, S0y);
            S1x = fmaf(pw1, z1x, S1x);  S1y = fmaf(pw1, z1y, S1y);
            S2x = fmaf(pw2, z2x, S2x);  S2y = fmaf(pw2, z2y, S2y);
            pw0 *= BE0; pw1 *= BE1; pw2 *= BE2;
        };

        #pragma unroll 8
        for (int k = 0; k < CHUNK - P; ++k) {      // 56 iters, 8 | 56, slot const
            const int slot = k & (P - 1);
            const float dx = bp[slot].x - bq[slot].x;
            const float dy = bp[slot].y - bq[slot].y;
            bp[slot] = p2[(k + P) * (CC / 2)];
            bq[slot] = q2[(k + P) * (CC / 2)];
            step(dx, dy);
        }
        #pragma unroll
        for (int k = CHUNK - P; k < CHUNK; ++k) {  // drain, fully unrolled
            const int slot = k & (P - 1);
            step(bp[slot].x - bq[slot].x, bp[slot].y - bq[slot].y);
        }

        const int wl = w * 32 + lane;
        sS[0 * THREADS + wl] = S0x;  sS[1 * THREADS + wl] = S0y;
        sS[2 * THREADS + wl] = S1x;  sS[3 * THREADS + wl] = S1y;
        sS[4 * THREADS + wl] = S2x;  sS[5 * THREADS + wl] = S2y;
        sE[0 * THREADS + wl] = z0x;  sE[1 * THREADS + wl] = z0y;
        sE[2 * THREADS + wl] = z1x;  sE[3 * THREADS + wl] = z1y;
        sE[4 * THREADS + wl] = z2x;  sE[5 * THREADS + wl] = z2y;

        if (chunk == 0) {                // virtual carry: C0 = d at t=0
            g_D0[0 * (BB * 32) + b * 32 + lane] = d0x;
            g_D0[1 * (BB * 32) + b * 32 + lane] = d0y;
        }

        float ap = W0f * (A0x + A0y) + W1f * (A1x + A1y) + W2f * (A2x + A2y);
        #pragma unroll
        for (int off = 16; off; off >>= 1)
            ap += __shfl_xor_sync(0xffffffffu, ap, off);
        if (lane == 0) sA[w] = ap;
    }
    __syncthreads();

    // ---- fold 8 chunks -> one 512-row segment (P,Q,L) per (ac, lane) ----
    if (tid < 6 * 32) {
        const int ac    = tid >> 5;
        const int lane2 = tid & 31;
        const int a     = ac >> 1;
        const float bl = BL_F(a);
        const float G  = G_F(a);

        float m = 1.f, L = 0.f, Pv = 0.f, Qv = 0.f;
        #pragma unroll
        for (int j = 0; j < WPB; ++j) {
            const float Sv = sS[ac * THREADS + j * 32 + lane2];
            const float Ev = sE[ac * THREADS + j * 32 + lane2];
            Pv += 2.f * L * Sv + L * L * G;
            Qv += 2.f * m * fmaf(G, L, Sv);
            m *= bl;
            L  = fmaf(bl, L, Ev);
        }
        const int chain = ac * (BB * 32) + b * 32 + lane2;
        g_P[bs * NCHAIN + chain] = Pv;
        g_Q[bs * NCHAIN + chain] = Qv;
        g_L[bs * NCHAIN + chain] = L;
    }
    if (tid == 0) {
        float apb = 0.f;
        #pragma unroll
        for (int i = 0; i < WPB; ++i) apb += sA[i];
        g_Ap[blockIdx.x] = apb;
    }
}

// ============ Kernel 2: 8-segment carry scan per chain + final reduce ============
__global__ __launch_bounds__(THREADS2) void ema_k2(float* __restrict__ out)
{
    const int tid  = threadIdx.x;
    const int s    = tid >> 5;                 // segment 0..7 (one warp each)
    const int lane = tid & 31;                 // chain-local
    const int ac   = blockIdx.x >> 6;          // 0..5
    const int b    = blockIdx.x & (BB - 1);
    const int a    = ac >> 1;

    const int idx = s * NCHAIN + blockIdx.x * 32 + lane;   // coalesced per warp
    const float Pv = g_P[idx];
    const float Qv = g_Q[idx];
    const float Lv = g_L[idx];

    __shared__ float sP[NBSEG * 32], sQ[NBSEG * 32], sL[NBSEG * 32];
    sP[s * 32 + lane] = Pv;  sQ[s * 32 + lane] = Qv;  sL[s * 32 + lane] = Lv;
    __syncthreads();

    if (tid < 32) {                            // warp 0 scans 8 segments per chain
        const int comp = ac & 1;
        const float Rc = R512_F(a);
        const float M  = M512_F(a);
        const float Wt = W_F(a);

        float C = g_D0[comp * (BB * 32) + b * 32 + tid];
        float loss = 0.f;
        #pragma unroll
        for (int ss = 0; ss < NBSEG; ++ss) {
            const int j = ss * 32 + tid;
            loss += sP[j] + sQ[j] * C + Rc * C * C;
            C = fmaf(M, C, sL[j]);
        }
        float v = Wt * loss;
        #pragma unroll
        for (int off = 16; off; off >>= 1)
            v += __shfl_xor_sync(0xffffffffu, v, off);
        if (tid == 0) g_p2[blockIdx.x] = v;
    }

    // deterministic last-block final reduce (cross terms + A partials)
    __threadfence();
    __syncthreads();
    __shared__ unsigned int s_isLast;
    if (tid == 0) {
        unsigned int tk = atomicAdd(&g_count2, 1u);
        s_isLast = (tk == (unsigned int)(GRID2 - 1));
    }
    __syncthreads();
    if (s_isLast) {
        float w = 0.f;
        for (int i = tid; i < GRID2; i += THREADS2) w += g_p2[i];
        for (int i = tid; i < GRID1; i += THREADS2) w += g_Ap[i];
        #pragma unroll
        for (int off = 16; off; off >>= 1)
            w += __shfl_xor_sync(0xffffffffu, w, off);
        __shared__ float sm2[8];
        if ((tid & 31) == 0) sm2[tid >> 5] = w;
        __syncthreads();
        if (tid == 0) {
            float tot = 0.f;
            #pragma unroll
            for (int i = 0; i < 8; ++i) tot += sm2[i];
            out[0] = tot * (1.0f / ((float)BB * (float)TT * (float)CC));
            g_count2 = 0;
        }
    }
}

extern "C" void kernel_launch(void* const* d_in, const int* in_sizes, int n_in,
                              void* d_out, int out_size)
{
    const float* pred = (const float*)d_in[0];
    const float* targ = (const float*)d_in[1];
    float* out = (float*)d_out;
    (void)in_sizes; (void)n_in; (void)out_size;

    ema_k1<<<GRID1, THREADS>>>(pred, targ);
    ema_k2<<<GRID2, THREADS2>>>(out);
}

// round 16
// speedup vs baseline: 1.1404x; 1.1404x over previous
#include <cuda_runtime.h>

// MultiScaleTrendLoss: loss = mean_{b,t,c} sum_i w_i * ema(pred-target, a_i)[b,t,c]^2
// Exact chunked EMA: y_k = z_k + beta^{k+1} * C. Single kernel, per-b ticket:
// Phase A: 8 warps/block = 8 consecutive 64-row chunks of one b (P=4 pipeline,
// proven); per-chunk (S,E) -> smem -> folded to one 512-row segment (P,Q,L).
// The LAST-arriving block of each b scans that b's 8 segments (L2-hot, 4.6KB)
// and writes the per-b loss; the last b-finisher ticket-reduces 64 values.

#define BB 64
#define TT 4096
#define CC 64
#define CHUNK 64
#define NCHUNK (TT / CHUNK)             // 64
#define WPB 8                           // warps (=chunks) per block
#define NBSEG (NCHUNK / WPB)            // 8 segments per b
#define GRID1 (BB * NBSEG)              // 512
#define THREADS 256
#define NCHAIN (3 * 2 * BB * 32)        // 12288 chains (ac, b, lane)

#define AL0 0.1f
#define AL1 0.3f
#define AL2 0.5f
#define BE0 0.9f
#define BE1 0.7f
#define BE2 0.5f
#define W0f 0.5f
#define W1f 0.3f
#define W2f 0.2f

__host__ __device__ constexpr double dpow(double b, int n) {
    double r = 1.0; for (int i = 0; i < n; ++i) r *= b; return r;
}
__host__ __device__ constexpr double gsum(double beta, int L) {   // sum_{k=1..L} beta^{2k}
    double q = beta * beta; return q * (1.0 - dpow(q, L)) / (1.0 - q);
}
__host__ __device__ constexpr double geo0(double x, int n) {      // sum_{k=0..n-1} x^k
    double s = 0.0, p = 1.0; for (int k = 0; k < n; ++k) { s += p; p *= x; } return s;
}

__device__ __forceinline__ float pick3(int a, float x0, float x1, float x2) {
    return (a == 0) ? x0 : ((a == 1) ? x1 : x2);
}
// chunk-level (64 rows)
#define BL_F(a)   pick3(a, (float)dpow(0.9, CHUNK), (float)dpow(0.7, CHUNK), (float)dpow(0.5, CHUNK))
#define G_F(a)    pick3(a, (float)gsum(0.9, CHUNK), (float)gsum(0.7, CHUNK), (float)gsum(0.5, CHUNK))
// segment-level (512 rows = 8 chunks)
#define M512_F(a) pick3(a, (float)dpow(0.9, CHUNK * WPB), \
                           (float)dpow(0.7, CHUNK * WPB), \
                           (float)dpow(0.5, CHUNK * WPB))
#define R512_F(a) pick3(a, (float)(gsum(0.9, CHUNK) * geo0(dpow(0.9, 2 * CHUNK), WPB)), \
                           (float)(gsum(0.7, CHUNK) * geo0(dpow(0.7, 2 * CHUNK), WPB)), \
                           (float)(gsum(0.5, CHUNK) * geo0(dpow(0.5, 2 * CHUNK), WPB)))
#define W_F(a)    pick3(a, W0f, W1f, W2f)

__device__ float g_P[NBSEG * NCHAIN];
__device__ float g_Q[NBSEG * NCHAIN];
__device__ float g_L[NBSEG * NCHAIN];
__device__ float g_Ap[GRID1];
__device__ float g_D0[2 * BB * 32];
__device__ float g_pb[BB];
__device__ unsigned int g_cnt[BB];      // zero-initialized; reset by each b-finisher
__device__ unsigned int g_tick = 0;

__global__ __launch_bounds__(THREADS) void ema_all(
    const float* __restrict__ pred, const float* __restrict__ targ,
    float* __restrict__ out)
{
    const int tid  = threadIdx.x;
    const int w    = tid >> 5;
    const int lane = tid & 31;
    const int b    = blockIdx.x >> 3;            // / NBSEG
    const int bs   = blockIdx.x & (NBSEG - 1);
    const int chunk = bs * WPB + w;              // 0..63

    __shared__ float sS[6 * THREADS];            // phase A: [ac][w*32+lane]; phase B: P
    __shared__ float sE[6 * THREADS];            // phase A: E;               phase B: Q
    __shared__ float sL3[6 * THREADS / 2 * 2];   // phase B: L (6*256)
    __shared__ float sA[WPB];

    // ================= Phase A: stream data once (proven P=4 loop) =================
    {
        const float2* __restrict__ p2 = reinterpret_cast<const float2*>(pred)
                                        + (b * TT + chunk * CHUNK) * (CC / 2) + lane;
        const float2* __restrict__ q2 = reinterpret_cast<const float2*>(targ)
                                        + (b * TT + chunk * CHUNK) * (CC / 2) + lane;

        constexpr int P = 4;
        float2 bp[P], bq[P];
        #pragma unroll
        for (int i = 0; i < P; ++i) { bp[i] = p2[i * (CC / 2)]; bq[i] = q2[i * (CC / 2)]; }

        float z0x = 0.f, z0y = 0.f, z1x = 0.f, z1y = 0.f, z2x = 0.f, z2y = 0.f;
        float A0x = 0.f, A0y = 0.f, A1x = 0.f, A1y = 0.f, A2x = 0.f, A2y = 0.f;
        float S0x = 0.f, S0y = 0.f, S1x = 0.f, S1y = 0.f, S2x = 0.f, S2y = 0.f;
        float pw0 = BE0, pw1 = BE1, pw2 = BE2;

        const float d0x = bp[0].x - bq[0].x;
        const float d0y = bp[0].y - bq[0].y;

        auto step = [&](float dx, float dy) {
            z0x = fmaf(AL0, dx - z0x, z0x);  z0y = fmaf(AL0, dy - z0y, z0y);
            z1x = fmaf(AL1, dx - z1x, z1x);  z1y = fmaf(AL1, dy - z1y, z1y);
            z2x = fmaf(AL2, dx - z2x, z2x);  z2y = fmaf(AL2, dy - z2y, z2y);
            A0x = fmaf(z0x, z0x, A0x);  A0y = fmaf(z0y, z0y, A0y);
            A1x = fmaf(z1x, z1x, A1x);  A1y = fmaf(z1y, z1y, A1y);
            A2x = fmaf(z2x, z2x, A2x);  A2y = fmaf(z2y, z2y, A2y);
            S0x = fmaf(pw0, z0x, S0x);  S0y = fmaf(pw0, z0y, S0y);
            S1x = fmaf(pw1, z1x, S1x);  S1y = fmaf(pw1, z1y, S1y);
            S2x = fmaf(pw2, z2x, S2x);  S2y = fmaf(pw2, z2y, S2y);
            pw0 *= BE0; pw1 *= BE1; pw2 *= BE2;
        };

        #pragma unroll 8
        for (int k = 0; k < CHUNK - P; ++k) {
            const int slot = k & (P - 1);
            const float dx = bp[slot].x - bq[slot].x;
            const float dy = bp[slot].y - bq[slot].y;
            bp[slot] = p2[(k + P) * (CC / 2)];
            bq[slot] = q2[(k + P) * (CC / 2)];
            step(dx, dy);
        }
        #pragma unroll
        for (int k = CHUNK - P; k < CHUNK; ++k) {
            const int slot = k & (P - 1);
            step(bp[slot].x - bq[slot].x, bp[slot].y - bq[slot].y);
        }

        const int wl = w * 32 + lane;
        sS[0 * THREADS + wl] = S0x;  sS[1 * THREADS + wl] = S0y;
        sS[2 * THREADS + wl] = S1x;  sS[3 * THREADS + wl] = S1y;
        sS[4 * THREADS + wl] = S2x;  sS[5 * THREADS + wl] = S2y;
        sE[0 * THREADS + wl] = z0x;  sE[1 * THREADS + wl] = z0y;
        sE[2 * THREADS + wl] = z1x;  sE[3 * THREADS + wl] = z1y;
        sE[4 * THREADS + wl] = z2x;  sE[5 * THREADS + wl] = z2y;

        if (chunk == 0) {                // virtual carry: C0 = d at t=0
            g_D0[0 * (BB * 32) + b * 32 + lane] = d0x;
            g_D0[1 * (BB * 32) + b * 32 + lane] = d0y;
        }

        float ap = W0f * (A0x + A0y) + W1f * (A1x + A1y) + W2f * (A2x + A2y);
        #pragma unroll
        for (int off = 16; off; off >>= 1)
            ap += __shfl_xor_sync(0xffffffffu, ap, off);
        if (lane == 0) sA[w] = ap;
    }
    __syncthreads();

    // ---- fold 8 chunks -> one 512-row segment (P,Q,L) per (ac, lane) ----
    if (tid < 6 * 32) {
        const int ac    = tid >> 5;
        const int lane2 = tid & 31;
        const int a     = ac >> 1;
        const float bl = BL_F(a);
        const float G  = G_F(a);

        float m = 1.f, L = 0.f, Pv = 0.f, Qv = 0.f;
        #pragma unroll
        for (int j = 0; j < WPB; ++j) {
            const float Sv = sS[ac * THREADS + j * 32 + lane2];
            const float Ev = sE[ac * THREADS + j * 32 + lane2];
            Pv += 2.f * L * Sv + L * L * G;
            Qv += 2.f * m * fmaf(G, L, Sv);
            m *= bl;
            L  = fmaf(bl, L, Ev);
        }
        const int chain = ac * (BB * 32) + b * 32 + lane2;
        g_P[bs * NCHAIN + chain] = Pv;
        g_Q[bs * NCHAIN + chain] = Qv;
        g_L[bs * NCHAIN + chain] = L;
    }
    if (tid == 0) {
        float apb = 0.f;
        #pragma unroll
        for (int i = 0; i < WPB; ++i) apb += sA[i];
        g_Ap[blockIdx.x] = apb;
    }

    // ================= per-b ticket: 8th arriver of this b does the scan =================
    __threadfence();                     // release this block's P/Q/L/Ap/D0 stores
    __syncthreads();
    __shared__ unsigned int s_last;
    if (tid == 0)
        s_last = (atomicAdd(&g_cnt[b], 1u) == (unsigned int)(NBSEG - 1));
    __syncthreads();
    if (!s_last) return;
    __threadfence();                     // acquire peers' stores

    // ---- load this b's 8 segments x 6 ac x 32 lanes (coalesced, L2-hot) ----
    {
        const int s_ = tid >> 5;         // segment 0..7
        const int ln = tid & 31;
        #pragma unroll
        for (int ac = 0; ac < 6; ++ac) {
            const int gidx = s_ * NCHAIN + ac * (BB * 32) + b * 32 + ln;
            const int sidx = ac * THREADS + s_ * 32 + ln;
            sS[sidx]  = g_P[gidx];
            sE[sidx]  = g_Q[gidx];
            sL3[sidx] = g_L[gidx];
        }
    }
    __syncthreads();

    // ---- scan 8 segments per chain; 6 warps = 6 ac ----
    __shared__ float sPart[6];
    if (tid < 6 * 32) {
        const int ac   = tid >> 5;
        const int ln   = tid & 31;
        const int a    = ac >> 1;
        const int comp = ac & 1;
        const float Rc = R512_F(a);
        const float M  = M512_F(a);
        const float Wt = W_F(a);

        float C = g_D0[comp * (BB * 32) + b * 32 + ln];
        float loss = 0.f;
        #pragma unroll
        for (int ss = 0; ss < NBSEG; ++ss) {
            const int j = ac * THREADS + ss * 32 + ln;
            loss += sS[j] + sE[j] * C + Rc * C * C;
            C = fmaf(M, C, sL3[j]);
        }
        float v = Wt * loss;
        #pragma unroll
        for (int off = 16; off; off >>= 1)
            v += __shfl_xor_sync(0xffffffffu, v, off);
        if (ln == 0) sPart[ac] = v;
    }
    __syncthreads();

    // ---- per-b total -> global ticket over 64 b's ----
    if (tid == 0) {
        float tot = 0.f;
        #pragma unroll
        for (int i = 0; i < 6; ++i) tot += sPart[i];
        #pragma unroll
        for (int i = 0; i < NBSEG; ++i) tot += g_Ap[b * NBSEG + i];
        g_pb[b] = tot;
        g_cnt[b] = 0;                    // reset for next graph replay
        __threadfence();
        unsigned int tk = atomicAdd(&g_tick, 1u);
        if (tk == (unsigned int)(BB - 1)) {
            __threadfence();
            float wv = 0.f;
            #pragma unroll
            for (int i = 0; i < BB; ++i) wv += g_pb[i];
            out[0] = wv * (1.0f / ((float)BB * (float)TT * (float)CC));
            g_tick = 0;                  // reset for next graph replay
        }
    }
}

extern "C" void kernel_launch(void* const* d_in, const int* in_sizes, int n_in,
                              void* d_out, int out_size)
{
    const float* pred = (const float*)d_in[0];
    const float* targ = (const float*)d_in[1];
    float* out = (float*)d_out;
    (void)in_sizes; (void)n_in; (void)out_size;

    ema_all<<<GRID1, THREADS>>>(pred, targ, out);
}

// round 17
// speedup vs baseline: 1.1427x; 1.0021x over previous
#include <cuda_runtime.h>

// MultiScaleTrendLoss: loss = mean_{b,t,c} sum_i w_i * ema(pred-target, a_i)[b,t,c]^2
// Exact chunked EMA: y_k = z_k + beta^{k+1} * C. Single kernel, per-b ticket.
// Phase A inner loop uses packed f32x2 math (FFMA2) — x/y channel pair per op.
// 8 warps/block = 8 consecutive 64-row chunks of one b; per-chunk (S,E) -> smem
// -> folded to one 512-row segment (P,Q,L). Last-arriving block of each b scans
// its 8 segments; last b-finisher ticket-reduces 64 values.

#define BB 64
#define TT 4096
#define CC 64
#define CHUNK 64
#define NCHUNK (TT / CHUNK)             // 64
#define WPB 8                           // warps (=chunks) per block
#define NBSEG (NCHUNK / WPB)            // 8 segments per b
#define GRID1 (BB * NBSEG)              // 512
#define THREADS 256
#define NCHAIN (3 * 2 * BB * 32)        // 12288 chains (ac, b, lane)

#define AL0 0.1f
#define AL1 0.3f
#define AL2 0.5f
#define BE0 0.9f
#define BE1 0.7f
#define BE2 0.5f
#define W0f 0.5f
#define W1f 0.3f
#define W2f 0.2f

typedef unsigned long long u64;

__device__ __forceinline__ u64 pack2(float x, float y) {
    u64 r; asm("mov.b64 %0, {%1,%2};" : "=l"(r) : "f"(x), "f"(y)); return r;
}
__device__ __forceinline__ float2 unpack2(u64 v) {
    float2 f; asm("mov.b64 {%0,%1}, %2;" : "=f"(f.x), "=f"(f.y) : "l"(v)); return f;
}
__device__ __forceinline__ u64 fma2(u64 a, u64 b, u64 c) {
    u64 d; asm("fma.rn.f32x2 %0, %1, %2, %3;" : "=l"(d) : "l"(a), "l"(b), "l"(c)); return d;
}
__device__ __forceinline__ u64 mul2(u64 a, u64 b) {
    u64 d; asm("mul.rn.f32x2 %0, %1, %2;" : "=l"(d) : "l"(a), "l"(b)); return d;
}

__host__ __device__ constexpr double dpow(double b, int n) {
    double r = 1.0; for (int i = 0; i < n; ++i) r *= b; return r;
}
__host__ __device__ constexpr double gsum(double beta, int L) {   // sum_{k=1..L} beta^{2k}
    double q = beta * beta; return q * (1.0 - dpow(q, L)) / (1.0 - q);
}
__host__ __device__ constexpr double geo0(double x, int n) {      // sum_{k=0..n-1} x^k
    double s = 0.0, p = 1.0; for (int k = 0; k < n; ++k) { s += p; p *= x; } return s;
}

__device__ __forceinline__ float pick3(int a, float x0, float x1, float x2) {
    return (a == 0) ? x0 : ((a == 1) ? x1 : x2);
}
// chunk-level (64 rows)
#define BL_F(a)   pick3(a, (float)dpow(0.9, CHUNK), (float)dpow(0.7, CHUNK), (float)dpow(0.5, CHUNK))
#define G_F(a)    pick3(a, (float)gsum(0.9, CHUNK), (float)gsum(0.7, CHUNK), (float)gsum(0.5, CHUNK))
// segment-level (512 rows = 8 chunks)
#define M512_F(a) pick3(a, (float)dpow(0.9, CHUNK * WPB), \
                           (float)dpow(0.7, CHUNK * WPB), \
                           (float)dpow(0.5, CHUNK * WPB))
#define R512_F(a) pick3(a, (float)(gsum(0.9, CHUNK) * geo0(dpow(0.9, 2 * CHUNK), WPB)), \
                           (float)(gsum(0.7, CHUNK) * geo0(dpow(0.7, 2 * CHUNK), WPB)), \
                           (float)(gsum(0.5, CHUNK) * geo0(dpow(0.5, 2 * CHUNK), WPB)))
#define W_F(a)    pick3(a, W0f, W1f, W2f)

__device__ float g_P[NBSEG * NCHAIN];
__device__ float g_Q[NBSEG * NCHAIN];
__device__ float g_L[NBSEG * NCHAIN];
__device__ float g_Ap[GRID1];
__device__ float g_D0[2 * BB * 32];
__device__ float g_pb[BB];
__device__ unsigned int g_cnt[BB];      // zero-init; reset by each b-finisher
__device__ unsigned int g_tick = 0;

__global__ __launch_bounds__(THREADS) void ema_all(
    const float* __restrict__ pred, const float* __restrict__ targ,
    float* __restrict__ out)
{
    const int tid  = threadIdx.x;
    const int w    = tid >> 5;
    const int lane = tid & 31;
    const int b    = blockIdx.x >> 3;            // / NBSEG
    const int bs   = blockIdx.x & (NBSEG - 1);
    const int chunk = bs * WPB + w;              // 0..63

    __shared__ float sS[6 * THREADS];            // phase A: S; phase B: P
    __shared__ float sE[6 * THREADS];            // phase A: E; phase B: Q
    __shared__ float sL3[6 * THREADS];           // phase B: L
    __shared__ float sA[WPB];

    // ================= Phase A: stream data once, packed f32x2 math =================
    {
        const u64* __restrict__ p8 = reinterpret_cast<const u64*>(pred)
                                     + (b * TT + chunk * CHUNK) * (CC / 2) + lane;
        const u64* __restrict__ q8 = reinterpret_cast<const u64*>(targ)
                                     + (b * TT + chunk * CHUNK) * (CC / 2) + lane;

        constexpr int P = 4;
        u64 bp[P], bq[P];
        #pragma unroll
        for (int i = 0; i < P; ++i) { bp[i] = p8[i * (CC / 2)]; bq[i] = q8[i * (CC / 2)]; }

        const u64 NEG1 = pack2(-1.f, -1.f);
        const u64 AL0p = pack2(AL0, AL0), AL1p = pack2(AL1, AL1), AL2p = pack2(AL2, AL2);
        const u64 BE0p = pack2(BE0, BE0), BE1p = pack2(BE1, BE1), BE2p = pack2(BE2, BE2);

        u64 z0 = 0ull, z1 = 0ull, z2 = 0ull;
        u64 A0 = 0ull, A1 = 0ull, A2 = 0ull;
        u64 S0 = 0ull, S1 = 0ull, S2 = 0ull;
        u64 pw0 = BE0p, pw1 = BE1p, pw2 = BE2p;  // beta^{k+1} duplicated pair

        const float2 d0f = unpack2(fma2(bq[0], NEG1, bp[0]));   // d at t0 of chunk

        auto step = [&](u64 p, u64 q) {
            const u64 d  = fma2(q, NEG1, p);                    // d = p - q
            const u64 t0 = fma2(z0, NEG1, d);  z0 = fma2(AL0p, t0, z0);
            const u64 t1 = fma2(z1, NEG1, d);  z1 = fma2(AL1p, t1, z1);
            const u64 t2 = fma2(z2, NEG1, d);  z2 = fma2(AL2p, t2, z2);
            A0 = fma2(z0, z0, A0);
            A1 = fma2(z1, z1, A1);
            A2 = fma2(z2, z2, A2);
            S0 = fma2(pw0, z0, S0);
            S1 = fma2(pw1, z1, S1);
            S2 = fma2(pw2, z2, S2);
            pw0 = mul2(pw0, BE0p);  pw1 = mul2(pw1, BE1p);  pw2 = mul2(pw2, BE2p);
        };

        #pragma unroll 8
        for (int k = 0; k < CHUNK - P; ++k) {
            const int slot = k & (P - 1);
            const u64 pv = bp[slot], qv = bq[slot];
            bp[slot] = p8[(k + P) * (CC / 2)];
            bq[slot] = q8[(k + P) * (CC / 2)];
            step(pv, qv);
        }
        #pragma unroll
        for (int k = CHUNK - P; k < CHUNK; ++k) {
            const int slot = k & (P - 1);
            step(bp[slot], bq[slot]);
        }

        const float2 S0f = unpack2(S0), S1f = unpack2(S1), S2f = unpack2(S2);
        const float2 z0f = unpack2(z0), z1f = unpack2(z1), z2f = unpack2(z2);
        const float2 A0f = unpack2(A0), A1f = unpack2(A1), A2f = unpack2(A2);

        const int wl = w * 32 + lane;
        sS[0 * THREADS + wl] = S0f.x;  sS[1 * THREADS + wl] = S0f.y;
        sS[2 * THREADS + wl] = S1f.x;  sS[3 * THREADS + wl] = S1f.y;
        sS[4 * THREADS + wl] = S2f.x;  sS[5 * THREADS + wl] = S2f.y;
        sE[0 * THREADS + wl] = z0f.x;  sE[1 * THREADS + wl] = z0f.y;
        sE[2 * THREADS + wl] = z1f.x;  sE[3 * THREADS + wl] = z1f.y;
        sE[4 * THREADS + wl] = z2f.x;  sE[5 * THREADS + wl] = z2f.y;

        if (chunk == 0) {                // virtual carry: C0 = d at t=0
            g_D0[0 * (BB * 32) + b * 32 + lane] = d0f.x;
            g_D0[1 * (BB * 32) + b * 32 + lane] = d0f.y;
        }

        float ap = W0f * (A0f.x + A0f.y) + W1f * (A1f.x + A1f.y) + W2f * (A2f.x + A2f.y);
        #pragma unroll
        for (int off = 16; off; off >>= 1)
            ap += __shfl_xor_sync(0xffffffffu, ap, off);
        if (lane == 0) sA[w] = ap;
    }
    __syncthreads();

    // ---- fold 8 chunks -> one 512-row segment (P,Q,L) per (ac, lane) ----
    if (tid < 6 * 32) {
        const int ac    = tid >> 5;
        const int lane2 = tid & 31;
        const int a     = ac >> 1;
        const float bl = BL_F(a);
        const float G  = G_F(a);

        float m = 1.f, L = 0.f, Pv = 0.f, Qv = 0.f;
        #pragma unroll
        for (int j = 0; j < WPB; ++j) {
            const float Sv = sS[ac * THREADS + j * 32 + lane2];
            const float Ev = sE[ac * THREADS + j * 32 + lane2];
            Pv += 2.f * L * Sv + L * L * G;
            Qv += 2.f * m * fmaf(G, L, Sv);
            m *= bl;
            L  = fmaf(bl, L, Ev);
        }
        const int chain = ac * (BB * 32) + b * 32 + lane2;
        g_P[bs * NCHAIN + chain] = Pv;
        g_Q[bs * NCHAIN + chain] = Qv;
        g_L[bs * NCHAIN + chain] = L;
    }
    if (tid == 0) {
        float apb = 0.f;
        #pragma unroll
        for (int i = 0; i < WPB; ++i) apb += sA[i];
        g_Ap[blockIdx.x] = apb;
    }

    // ================= per-b ticket: 8th arriver of this b does the scan =================
    __threadfence();                     // release this block's P/Q/L/Ap/D0 stores
    __syncthreads();
    __shared__ unsigned int s_last;
    if (tid == 0)
        s_last = (atomicAdd(&g_cnt[b], 1u) == (unsigned int)(NBSEG - 1));
    __syncthreads();
    if (!s_last) return;
    __threadfence();                     // acquire peers' stores

    // ---- load this b's 8 segments x 6 ac x 32 lanes (coalesced, L2-hot) ----
    {
        const int s_ = tid >> 5;         // segment 0..7
        const int ln = tid & 31;
        #pragma unroll
        for (int ac = 0; ac < 6; ++ac) {
            const int gidx = s_ * NCHAIN + ac * (BB * 32) + b * 32 + ln;
            const int sidx = ac * THREADS + s_ * 32 + ln;
            sS[sidx]  = g_P[gidx];
            sE[sidx]  = g_Q[gidx];
            sL3[sidx] = g_L[gidx];
        }
    }
    __syncthreads();

    // ---- scan 8 segments per chain; 6 warps = 6 ac ----
    __shared__ float sPart[6];
    if (tid < 6 * 32) {
        const int ac   = tid >> 5;
        const int ln   = tid & 31;
        const int a    = ac >> 1;
        const int comp = ac & 1;
        const float Rc = R512_F(a);
        const float M  = M512_F(a);
        const float Wt = W_F(a);

        float C = g_D0[comp * (BB * 32) + b * 32 + ln];
        float loss = 0.f;
        #pragma unroll
        for (int ss = 0; ss < NBSEG; ++ss) {
            const int j = ac * THREADS + ss * 32 + ln;
            loss += sS[j] + sE[j] * C + Rc * C * C;
            C = fmaf(M, C, sL3[j]);
        }
        float v = Wt * loss;
        #pragma unroll
        for (int off = 16; off; off >>= 1)
            v += __shfl_xor_sync(0xffffffffu, v, off);
        if (ln == 0) sPart[ac] = v;
    }
    __syncthreads();

    // ---- per-b total -> global ticket over 64 b's ----
    if (tid == 0) {
        float tot = 0.f;
        #pragma unroll
        for (int i = 0; i < 6; ++i) tot += sPart[i];
        #pragma unroll
        for (int i = 0; i < NBSEG; ++i) tot += g_Ap[b * NBSEG + i];
        g_pb[b] = tot;
        g_cnt[b] = 0;                    // reset for next graph replay
        __threadfence();
        unsigned int tk = atomicAdd(&g_tick, 1u);
        if (tk == (unsigned int)(BB - 1)) {
            __threadfence();
            float wv = 0.f;
            #pragma unroll
            for (int i = 0; i < BB; ++i) wv += g_pb[i];
            out[0] = wv * (1.0f / ((float)BB * (float)TT * (float)CC));
            g_tick = 0;                  // reset for next graph replay
        }
    }
}

extern "C" void kernel_launch(void* const* d_in, const int* in_sizes, int n_in,
                              void* d_out, int out_size)
{
    const float* pred = (const float*)d_in[0];
    const float* targ = (const float*)d_in[1];
    float* out = (float*)d_out;
    (void)in_sizes; (void)n_in; (void)out_size;

    ema_all<<<GRID1, THREADS>>>(pred, targ, out);
}